// round 3
// baseline (speedup 1.0000x reference)
#include <cuda_runtime.h>

// ---------------------------------------------------------------------------
// FeatureRNN: 5-level tree MLP reduction.
//   K=2048 roots, B=4 branching, D=5 levels.
//   SIZES  = [2048, 8192, 32768, 131072, 524288]
//   NOFF   = [0, 2048, 10240, 43008, 174080, 698368]
//   BOFF   = [0, 8192, 40960, 172032, 696320]
//   net(x) = leaky( leaky(x @ W1 + b1) @ W2 + b2 ),  x = [msg(125)|bond(12)|out(40)]
// Leaf level: bond/out slots are zero -> only W1 rows [0,125) contribute.
// Parent levels: msg is repeated over B=4 children -> compute msg·W1 once/parent.
// ---------------------------------------------------------------------------

namespace {
constexpr int ATOM = 125;
constexpr int BOND = 12;
constexpr int OUTD = 40;

constexpr int N_LEAF  = 524288;
constexpr int NOFF4   = 174080;

// shared-memory layout (in floats)
constexpr int SW1 = 0;                 // W1 padded [177][128]
constexpr int SW2 = SW1 + 177 * 128;   // 22656, W2 [125][40]
constexpr int SB1 = SW2 + 125 * 40;    // 27656, b1 padded [128]
constexpr int SB2 = SB1 + 128;         // 27784, b2 padded [64]
constexpr int SHS = SB2 + 64;          // 27848, per-warp h staging [NWARPS][128]
constexpr int NTHREADS = 512;
constexpr int NWARPS   = NTHREADS / 32;            // 16
constexpr int SMEM_FLOATS = SHS + NWARPS * 128;    // 29896
constexpr int SMEM_BYTES  = SMEM_FLOATS * 4;       // 119584 (< 227 KB cap)
}

// Scratch (ping-pong level outputs). __device__ globals: allocation-free.
__device__ float g_buf0[524288 * 40];   // 84 MB
__device__ float g_buf1[131072 * 40];   // 21 MB

__device__ __forceinline__ float lrelu(float v) { return fmaxf(v, 0.01f * v); }

__device__ __forceinline__ void load_weights(float* s,
                                             const float* __restrict__ W1,
                                             const float* __restrict__ b1,
                                             const float* __restrict__ W2,
                                             const float* __restrict__ b2) {
    const int tid = threadIdx.x;
    for (int idx = tid; idx < 177 * 128; idx += NTHREADS) {
        int k = idx >> 7, j = idx & 127;
        s[SW1 + idx] = (j < 125) ? W1[k * 125 + j] : 0.f;
    }
    for (int idx = tid; idx < 125 * 40; idx += NTHREADS) s[SW2 + idx] = W2[idx];
    for (int idx = tid; idx < 128; idx += NTHREADS) s[SB1 + idx] = (idx < 125) ? b1[idx] : 0.f;
    for (int idx = tid; idx < 64;  idx += NTHREADS) s[SB2 + idx] = (idx < 40)  ? b2[idx] : 0.f;
    __syncthreads();
}

// Accumulate NT consecutive W1 rows into acc; xr holds x[k] on lane k (shfl broadcast).
// w points at &W1s[row0*128 + 4*lane]. Lane owns hidden cols [4*lane, 4*lane+4).
template <int NT>
__device__ __forceinline__ void l1_chunk(float4& acc, float xr, const float* __restrict__ w) {
#pragma unroll
    for (int t = 0; t < NT; t++) {
        float xv = __shfl_sync(0xffffffffu, xr, t);
        float4 wv = *reinterpret_cast<const float4*>(w + t * 128);
        acc.x = fmaf(xv, wv.x, acc.x);
        acc.y = fmaf(xv, wv.y, acc.y);
        acc.z = fmaf(xv, wv.z, acc.z);
        acc.w = fmaf(xv, wv.w, acc.w);
    }
}

// h (pre-activation, bias included) from the 125-wide msg slice of x.
__device__ __forceinline__ float4 layer1_msg(const float* __restrict__ xrow,
                                             const float* __restrict__ W1s,
                                             const float* __restrict__ b1s,
                                             int lane) {
    float4 acc = *reinterpret_cast<const float4*>(&b1s[4 * lane]);
    float xr0 = xrow[lane];
    float xr1 = xrow[lane + 32];
    float xr2 = xrow[lane + 64];
    float xr3 = (lane < 29) ? xrow[lane + 96] : 0.f;
    const float* w = &W1s[4 * lane];
    l1_chunk<32>(acc, xr0, w);
    l1_chunk<32>(acc, xr1, w + 32 * 128);
    l1_chunk<32>(acc, xr2, w + 64 * 128);
    l1_chunk<29>(acc, xr3, w + 96 * 128);
    return acc;
}

// y = h @ W2 + b2. Lane computes col=lane (0..31) and col=32+(lane&7) (valid for lane<8).
__device__ __forceinline__ void layer2(const float* __restrict__ hs,
                                       const float* __restrict__ W2s,
                                       const float* __restrict__ b2s,
                                       int lane, float& y0, float& y1) {
    const int c2 = 32 + (lane & 7);
    float a0 = b2s[lane];
    float a1 = b2s[c2];
#pragma unroll 5
    for (int k = 0; k < 125; k++) {
        float hv = hs[k];                       // broadcast, conflict-free
        a0 = fmaf(hv, W2s[k * 40 + lane], a0);
        a1 = fmaf(hv, W2s[k * 40 + c2],   a1);
    }
    y0 = a0; y1 = a1;
}

// ---------------- Leaf level: x = [msg | 0 | 0] -------------------------------
__global__ void __launch_bounds__(NTHREADS, 1)
leaf_kernel(const float* __restrict__ node_msg,
            const float* __restrict__ W1, const float* __restrict__ b1,
            const float* __restrict__ W2, const float* __restrict__ b2) {
    extern __shared__ float s[];
    load_weights(s, W1, b1, W2, b2);
    const float* W1s = s + SW1;
    const float* W2s = s + SW2;
    const float* b1s = s + SB1;
    const float* b2s = s + SB2;
    const int lane = threadIdx.x & 31;
    const int wib  = threadIdx.x >> 5;
    float* hs = s + SHS + wib * 128;

    const int gw = blockIdx.x * NWARPS + wib;
    const int nw = gridDim.x * NWARPS;
    for (int r = gw; r < N_LEAF; r += nw) {
        const float* xrow = node_msg + (long long)(NOFF4 + r) * ATOM;
        float4 h = layer1_msg(xrow, W1s, b1s, lane);
        h.x = lrelu(h.x); h.y = lrelu(h.y); h.z = lrelu(h.z); h.w = lrelu(h.w);
        __syncwarp();
        *reinterpret_cast<float4*>(&hs[4 * lane]) = h;
        __syncwarp();
        float y0, y1;
        layer2(hs, W2s, b2s, lane, y0, y1);
        float* orow = g_buf0 + (long long)r * OUTD;
        orow[lane] = lrelu(y0);
        if (lane < 8) orow[32 + lane] = lrelu(y1);
        __syncwarp();   // hs reused next row
    }
}

// ---------------- Inner levels: one warp per parent ---------------------------
__global__ void __launch_bounds__(NTHREADS, 1)
level_kernel(const float* __restrict__ node_msg,
             const float* __restrict__ bonds,
             const float* __restrict__ W1, const float* __restrict__ b1,
             const float* __restrict__ W2, const float* __restrict__ b2,
             int noff, long long boff, int nP,
             int child_sel, int parent_sel, float* final_out) {
    extern __shared__ float s[];
    load_weights(s, W1, b1, W2, b2);
    const float* W1s = s + SW1;
    const float* W2s = s + SW2;
    const float* b1s = s + SB1;
    const float* b2s = s + SB2;
    const int lane = threadIdx.x & 31;
    const int wib  = threadIdx.x >> 5;
    float* hs = s + SHS + wib * 128;

    const float* child = (child_sel == 0) ? g_buf0 : g_buf1;
    float* parent = (parent_sel == 2) ? final_out
                                      : ((parent_sel == 0) ? g_buf0 : g_buf1);

    const int gw = blockIdx.x * NWARPS + wib;
    const int nw = gridDim.x * NWARPS;
    for (int p = gw; p < nP; p += nw) {
        const float* xrow = node_msg + (long long)(noff + p) * ATOM;
        // msg contribution + bias: shared across the 4 children (pre-activation!)
        float4 hb = layer1_msg(xrow, W1s, b1s, lane);

        float ys0 = 0.f, ys1 = 0.f;
#pragma unroll 1
        for (int b = 0; b < 4; b++) {
            long long c = 4LL * p + b;
            const float* brow = bonds + (boff + c) * BOND;
            const float* orow = child + c * OUTD;
            // x slice k=125..176: [bond(12) | out(40)] packed into 2 shuffle regs
            float x0 = (lane < 12) ? brow[lane] : orow[lane - 12]; // k=125..156
            float x1 = (lane < 20) ? orow[20 + lane] : 0.f;        // k=157..176
            float4 h = hb;
            l1_chunk<32>(h, x0, &W1s[125 * 128 + 4 * lane]);
            l1_chunk<20>(h, x1, &W1s[157 * 128 + 4 * lane]);
            h.x = lrelu(h.x); h.y = lrelu(h.y); h.z = lrelu(h.z); h.w = lrelu(h.w);
            __syncwarp();
            *reinterpret_cast<float4*>(&hs[4 * lane]) = h;
            __syncwarp();
            float y0, y1;
            layer2(hs, W2s, b2s, lane, y0, y1);
            ys0 += lrelu(y0);
            ys1 += lrelu(y1);
            __syncwarp();   // hs reused next child
        }
        float* prow = parent + (long long)p * OUTD;
        prow[lane] = ys0;
        if (lane < 8) prow[32 + lane] = ys1;
    }
}

// ---------------------------------------------------------------------------
extern "C" void kernel_launch(void* const* d_in, const int* in_sizes, int n_in,
                              void* d_out, int out_size) {
    const float* node_msg = (const float*)d_in[0];
    const float* bonds    = (const float*)d_in[1];
    const float* W1       = (const float*)d_in[2];
    const float* b1       = (const float*)d_in[3];
    const float* W2       = (const float*)d_in[4];
    const float* b2       = (const float*)d_in[5];
    float* out = (float*)d_out;

    cudaFuncSetAttribute(leaf_kernel,  cudaFuncAttributeMaxDynamicSharedMemorySize, SMEM_BYTES);
    cudaFuncSetAttribute(level_kernel, cudaFuncAttributeMaxDynamicSharedMemorySize, SMEM_BYTES);

    const int blocks = 148;  // 1 persistent 512-thread block per SM

    // Level 4 (leaf): 524288 rows -> g_buf0
    leaf_kernel<<<blocks, NTHREADS, SMEM_BYTES>>>(node_msg, W1, b1, W2, b2);
    // Level 3: 131072 parents, children in g_buf0 -> g_buf1
    level_kernel<<<blocks, NTHREADS, SMEM_BYTES>>>(node_msg, bonds, W1, b1, W2, b2,
                                                   43008, 172032LL, 131072, 0, 1, nullptr);
    // Level 2: 32768 parents, g_buf1 -> g_buf0
    level_kernel<<<blocks, NTHREADS, SMEM_BYTES>>>(node_msg, bonds, W1, b1, W2, b2,
                                                   10240, 40960LL, 32768, 1, 0, nullptr);
    // Level 1: 8192 parents, g_buf0 -> g_buf1
    level_kernel<<<blocks, NTHREADS, SMEM_BYTES>>>(node_msg, bonds, W1, b1, W2, b2,
                                                   2048, 8192LL, 8192, 0, 1, nullptr);
    // Level 0: 2048 parents, g_buf1 -> d_out
    level_kernel<<<128, NTHREADS, SMEM_BYTES>>>(node_msg, bonds, W1, b1, W2, b2,
                                                0, 0LL, 2048, 1, 2, out);
}

// round 5
// speedup vs baseline: 2.4029x; 2.4029x over previous
#include <cuda_runtime.h>

// ---------------------------------------------------------------------------
// FeatureRNN: 5-level tree MLP reduction, register-blocked R=4 rows/warp.
//   SIZES  = [2048, 8192, 32768, 131072, 524288]
//   NOFF   = [0, 2048, 10240, 43008, 174080, 698368]
//   BOFF   = [0, 8192, 40960, 172032, 696320]
//   net(x) = leaky( leaky(x @ W1 + b1) @ W2 + b2 ),  x = [msg(125)|bond(12)|out(40)]
// Key fix vs R3 (L1=72.9%, fma=13.8%): every W1/W2 shared-mem load now feeds
// 4 rows' worth of FMAs (4 leaf rows / 4 parents / 4 same-slot children).
// ---------------------------------------------------------------------------

namespace {
constexpr int ATOM = 125;
constexpr int BOND = 12;
constexpr int OUTD = 40;

constexpr int N_LEAF = 524288;
constexpr int NOFF4  = 174080;

// shared-memory layout (floats)
constexpr int SW1 = 0;                  // W1 padded [177][128] (cols >=125 zero)
constexpr int SW2 = SW1 + 177 * 128;    // 22656: W2 padded [128][40] (rows >=125 zero)
constexpr int SB1 = SW2 + 128 * 40;     // 27776: b1 padded [128] (zeros >=125)
constexpr int SB2 = SB1 + 128;          // 27904: b2 padded [64]
constexpr int SHS = SB2 + 64;           // 27968: per-warp h staging [NWARPS][4][128]
constexpr int NTHREADS = 512;
constexpr int NWARPS   = NTHREADS / 32;              // 16
constexpr int SMEM_FLOATS = SHS + NWARPS * 4 * 128;  // 36160
constexpr int SMEM_BYTES  = SMEM_FLOATS * 4;         // 144640 B (< 227 KB cap)
}

// Scratch (ping-pong level outputs). __device__ globals: allocation-free.
__device__ float g_buf0[524288 * 40];   // 84 MB
__device__ float g_buf1[131072 * 40];   // 21 MB

__device__ __forceinline__ float lrelu(float v) { return fmaxf(v, 0.01f * v); }

__device__ __forceinline__ void load_weights(float* s,
                                             const float* __restrict__ W1,
                                             const float* __restrict__ b1,
                                             const float* __restrict__ W2,
                                             const float* __restrict__ b2) {
    const int tid = threadIdx.x;
    for (int idx = tid; idx < 177 * 128; idx += NTHREADS) {
        int k = idx >> 7, j = idx & 127;
        s[SW1 + idx] = (j < 125) ? W1[k * 125 + j] : 0.f;
    }
    for (int idx = tid; idx < 128 * 40; idx += NTHREADS) {
        int k = idx / 40;
        s[SW2 + idx] = (k < 125) ? W2[idx] : 0.f;
    }
    for (int idx = tid; idx < 128; idx += NTHREADS) s[SB1 + idx] = (idx < 125) ? b1[idx] : 0.f;
    for (int idx = tid; idx < 64;  idx += NTHREADS) s[SB2 + idx] = (idx < 40)  ? b2[idx] : 0.f;
    __syncthreads();
}

// Accumulate NT consecutive W1 rows into 4 rows' accumulators.
// xr[r] holds row r's x[k] on lane k; one LDS.128 of W1 feeds 16 FMAs.
template <int NT>
__device__ __forceinline__ void l1_chunk4(float4 acc[4], const float xr[4],
                                          const float* __restrict__ w) {
#pragma unroll 8
    for (int t = 0; t < NT; t++) {
        float4 wv = *reinterpret_cast<const float4*>(w + t * 128);
#pragma unroll
        for (int r = 0; r < 4; r++) {
            float xv = __shfl_sync(0xffffffffu, xr[r], t);
            acc[r].x = fmaf(xv, wv.x, acc[r].x);
            acc[r].y = fmaf(xv, wv.y, acc[r].y);
            acc[r].z = fmaf(xv, wv.z, acc[r].z);
            acc[r].w = fmaf(xv, wv.w, acc[r].w);
        }
    }
}

// Pre-activation h (bias included) for 4 consecutive rows' 125-wide msg slices.
__device__ __forceinline__ void layer1_msg4(float4 acc[4],
                                            const float* __restrict__ xbase,
                                            const float* __restrict__ W1s,
                                            const float* __restrict__ b1s,
                                            int lane) {
    float4 bias = *reinterpret_cast<const float4*>(&b1s[4 * lane]);
#pragma unroll
    for (int r = 0; r < 4; r++) acc[r] = bias;
    float a[4], b[4], c[4], d[4];
#pragma unroll
    for (int r = 0; r < 4; r++) {
        const float* x = xbase + r * ATOM;
        a[r] = x[lane];
        b[r] = x[lane + 32];
        c[r] = x[lane + 64];
        d[r] = (lane < 29) ? x[lane + 96] : 0.f;
    }
    const float* w = W1s + 4 * lane;
    l1_chunk4<32>(acc, a, w);
    l1_chunk4<32>(acc, b, w + 32 * 128);
    l1_chunk4<32>(acc, c, w + 64 * 128);
    l1_chunk4<29>(acc, d, w + 96 * 128);
}

// y = h @ W2 + b2 for 4 rows; one W2 column load pair serves all 4 rows.
// hs: [4][128], entries 125..127 are exactly zero. W2s rows 125..127 zero.
__device__ __forceinline__ void layer2_4(const float* __restrict__ hs,
                                         const float* __restrict__ W2s,
                                         const float* __restrict__ b2s,
                                         int lane, float y0[4], float y1[4]) {
    const int c2 = 32 + (lane & 7);
    float a0[4], a1[4];
    const float bb0 = b2s[lane], bb1 = b2s[c2];
#pragma unroll
    for (int r = 0; r < 4; r++) { a0[r] = bb0; a1[r] = bb1; }
#pragma unroll 4
    for (int k = 0; k < 128; k += 4) {
        float w00 = W2s[(k + 0) * 40 + lane];
        float w01 = W2s[(k + 1) * 40 + lane];
        float w02 = W2s[(k + 2) * 40 + lane];
        float w03 = W2s[(k + 3) * 40 + lane];
        float w10 = W2s[(k + 0) * 40 + c2];
        float w11 = W2s[(k + 1) * 40 + c2];
        float w12 = W2s[(k + 2) * 40 + c2];
        float w13 = W2s[(k + 3) * 40 + c2];
#pragma unroll
        for (int r = 0; r < 4; r++) {
            float4 hv = *reinterpret_cast<const float4*>(&hs[r * 128 + k]);
            a0[r] = fmaf(hv.x, w00, a0[r]);
            a0[r] = fmaf(hv.y, w01, a0[r]);
            a0[r] = fmaf(hv.z, w02, a0[r]);
            a0[r] = fmaf(hv.w, w03, a0[r]);
            a1[r] = fmaf(hv.x, w10, a1[r]);
            a1[r] = fmaf(hv.y, w11, a1[r]);
            a1[r] = fmaf(hv.z, w12, a1[r]);
            a1[r] = fmaf(hv.w, w13, a1[r]);
        }
    }
#pragma unroll
    for (int r = 0; r < 4; r++) { y0[r] = a0[r]; y1[r] = a1[r]; }
}

__device__ __forceinline__ void stage_h(float* __restrict__ hw, const float4 acc[4], int lane) {
#pragma unroll
    for (int r = 0; r < 4; r++) {
        float4 h = acc[r];
        h.x = lrelu(h.x); h.y = lrelu(h.y); h.z = lrelu(h.z); h.w = lrelu(h.w);
        *reinterpret_cast<float4*>(&hw[r * 128 + 4 * lane]) = h;
    }
    __syncwarp();
}

// ---------------- Leaf level: x = [msg | 0 | 0], 4 rows per warp -------------
__global__ void __launch_bounds__(NTHREADS, 1)
leaf_kernel(const float* __restrict__ node_msg,
            const float* __restrict__ W1, const float* __restrict__ b1,
            const float* __restrict__ W2, const float* __restrict__ b2) {
    extern __shared__ float s[];
    load_weights(s, W1, b1, W2, b2);
    const float* W1s = s + SW1;
    const float* W2s = s + SW2;
    const float* b1s = s + SB1;
    const float* b2s = s + SB2;
    const int lane = threadIdx.x & 31;
    const int wib  = threadIdx.x >> 5;
    float* hw = s + SHS + wib * 4 * 128;

    const int gw = blockIdx.x * NWARPS + wib;
    const int nw = gridDim.x * NWARPS;
    const int ntask = N_LEAF / 4;
    for (int g = gw; g < ntask; g += nw) {
        const float* xbase = node_msg + (long long)(NOFF4 + 4 * g) * ATOM;
        float4 acc[4];
        layer1_msg4(acc, xbase, W1s, b1s, lane);
        stage_h(hw, acc, lane);
        float y0[4], y1[4];
        layer2_4(hw, W2s, b2s, lane, y0, y1);
#pragma unroll
        for (int r = 0; r < 4; r++) {
            float* orow = g_buf0 + (long long)(4 * g + r) * OUTD;
            orow[lane] = lrelu(y0[r]);
            if (lane < 8) orow[32 + lane] = lrelu(y1[r]);
        }
        __syncwarp();   // hw reused next iteration
    }
}

// ---------------- Inner levels: 4 parents per warp ---------------------------
__global__ void __launch_bounds__(NTHREADS, 1)
level_kernel(const float* __restrict__ node_msg,
             const float* __restrict__ bonds,
             const float* __restrict__ W1, const float* __restrict__ b1,
             const float* __restrict__ W2, const float* __restrict__ b2,
             int noff, long long boff, int nP,
             int child_sel, int parent_sel, float* final_out) {
    extern __shared__ float s[];
    load_weights(s, W1, b1, W2, b2);
    const float* W1s = s + SW1;
    const float* W2s = s + SW2;
    const float* b1s = s + SB1;
    const float* b2s = s + SB2;
    const int lane = threadIdx.x & 31;
    const int wib  = threadIdx.x >> 5;
    float* hw = s + SHS + wib * 4 * 128;

    const float* child = (child_sel == 0) ? g_buf0 : g_buf1;
    float* parent = (parent_sel == 2) ? final_out
                                      : ((parent_sel == 0) ? g_buf0 : g_buf1);

    const int gw = blockIdx.x * NWARPS + wib;
    const int nw = gridDim.x * NWARPS;
    const int ntask = nP / 4;
    for (int g = gw; g < ntask; g += nw) {
        const int p0 = 4 * g;
        const float* xbase = node_msg + (long long)(noff + p0) * ATOM;
        // msg contribution + bias: shared across each parent's 4 children.
        float4 hb[4];
        layer1_msg4(hb, xbase, W1s, b1s, lane);

        float ys0[4] = {0.f, 0.f, 0.f, 0.f};
        float ys1[4] = {0.f, 0.f, 0.f, 0.f};
#pragma unroll 1
        for (int b = 0; b < 4; b++) {
            // row r = child b of parent (p0+r); the 4 rows share W1 panel loads
            float x0[4], x1[4];
#pragma unroll
            for (int r = 0; r < 4; r++) {
                long long c = 4LL * (p0 + r) + b;
                const float* brow = bonds + (boff + c) * BOND;
                const float* orow = child + c * OUTD;
                x0[r] = (lane < 12) ? brow[lane] : orow[lane - 12]; // k=125..156
                x1[r] = (lane < 20) ? orow[20 + lane] : 0.f;        // k=157..176
            }
            float4 h[4];
#pragma unroll
            for (int r = 0; r < 4; r++) h[r] = hb[r];
            l1_chunk4<32>(h, x0, &W1s[125 * 128 + 4 * lane]);
            l1_chunk4<20>(h, x1, &W1s[157 * 128 + 4 * lane]);
            stage_h(hw, h, lane);
            float y0[4], y1[4];
            layer2_4(hw, W2s, b2s, lane, y0, y1);
#pragma unroll
            for (int r = 0; r < 4; r++) {
                ys0[r] += lrelu(y0[r]);
                ys1[r] += lrelu(y1[r]);
            }
            __syncwarp();   // hw reused next child slot
        }
#pragma unroll
        for (int r = 0; r < 4; r++) {
            float* prow = parent + (long long)(p0 + r) * OUTD;
            prow[lane] = ys0[r];
            if (lane < 8) prow[32 + lane] = ys1[r];
        }
    }
}

// ---------------------------------------------------------------------------
extern "C" void kernel_launch(void* const* d_in, const int* in_sizes, int n_in,
                              void* d_out, int out_size) {
    const float* node_msg = (const float*)d_in[0];
    const float* bonds    = (const float*)d_in[1];
    const float* W1       = (const float*)d_in[2];
    const float* b1       = (const float*)d_in[3];
    const float* W2       = (const float*)d_in[4];
    const float* b2       = (const float*)d_in[5];
    float* out = (float*)d_out;

    cudaFuncSetAttribute(leaf_kernel,  cudaFuncAttributeMaxDynamicSharedMemorySize, SMEM_BYTES);
    cudaFuncSetAttribute(level_kernel, cudaFuncAttributeMaxDynamicSharedMemorySize, SMEM_BYTES);

    const int blocks = 148;  // 1 persistent 512-thread block per SM

    // Level 4 (leaf): 524288 rows -> g_buf0
    leaf_kernel<<<blocks, NTHREADS, SMEM_BYTES>>>(node_msg, W1, b1, W2, b2);
    // Level 3: 131072 parents, children in g_buf0 -> g_buf1
    level_kernel<<<blocks, NTHREADS, SMEM_BYTES>>>(node_msg, bonds, W1, b1, W2, b2,
                                                   43008, 172032LL, 131072, 0, 1, nullptr);
    // Level 2: 32768 parents, g_buf1 -> g_buf0
    level_kernel<<<blocks, NTHREADS, SMEM_BYTES>>>(node_msg, bonds, W1, b1, W2, b2,
                                                   10240, 40960LL, 32768, 1, 0, nullptr);
    // Level 1: 8192 parents, g_buf0 -> g_buf1
    level_kernel<<<blocks, NTHREADS, SMEM_BYTES>>>(node_msg, bonds, W1, b1, W2, b2,
                                                   2048, 8192LL, 8192, 0, 1, nullptr);
    // Level 0: 2048 parents, g_buf1 -> d_out
    level_kernel<<<blocks, NTHREADS, SMEM_BYTES>>>(node_msg, bonds, W1, b1, W2, b2,
                                                   0, 0LL, 2048, 1, 2, out);
}